// round 8
// baseline (speedup 1.0000x reference)
#include <cuda_runtime.h>
#include <cstdint>

// Masked cumulative sum along rows.
// x: [256, 131072] fp32; mask: [256, 131072] bool (delivered as u8 OR int32, order in d_in unknown).
// out = cumsum(where(mask, x, 0), axis=1)
//
// Strategy: single-pass decoupled look-back scan.
//   - 256 rows x 32 tiles/row = 8192 independent CTAs, 256 threads, 16 elems/thread (TILE=4096)
//   - tile state = one 64-bit word: [flag:32 | float_bits:32], release-store / acquire-load
//   - look-back depth <= 31 => one 32-lane window always resolves the exclusive prefix
//   - probe kernel classifies both input buffers (fp32 vs u8-mask vs i32-mask) to fix
//     both the mask dtype and any input-order swap at runtime (uniform, deterministic).

#define N_COLS 131072
#define B_ROWS 256
#define TPB 256
#define ITEMS 16
#define TILE (TPB * ITEMS)                 // 4096
#define TILES_PER_ROW (N_COLS / TILE)      // 32
#define NTILES (B_ROWS * TILES_PER_ROW)    // 8192

#define FLAG_INV  0u
#define FLAG_PART 1u
#define FLAG_INCL 2u

__device__ unsigned long long g_tile_state[NTILES];
__device__ int g_mask_idx;    // which of d_in[0]/d_in[1] is the mask
__device__ int g_mask_is_u8;  // 1 = u8 mask, 0 = int32 mask

__device__ __forceinline__ unsigned long long pack_state(unsigned flag, float v) {
    return ((unsigned long long)flag << 32) | (unsigned long long)__float_as_uint(v);
}

__device__ __forceinline__ void store_state(unsigned long long* p, unsigned long long v) {
    asm volatile("st.global.release.gpu.u64 [%0], %1;" :: "l"(p), "l"(v) : "memory");
}

__device__ __forceinline__ unsigned long long load_state(unsigned long long* p) {
    unsigned long long v;
    asm volatile("ld.global.acquire.gpu.u64 %0, [%1];" : "=l"(v) : "l"(p) : "memory");
    return v;
}

// Classify both inputs over a 16K-word (64 KiB) sample.
// word-class: all words <= 1            -> int32 0/1 mask
// byte-class: all bytes in {0,1}        -> u8 0/1 mask
// otherwise                             -> fp32 data
__global__ void probe_kernel(const unsigned* __restrict__ a,
                             const unsigned* __restrict__ b) {
    __shared__ int s_nw[2];   // "not all words 0/1"
    __shared__ int s_nb[2];   // "not all bytes 0/1"
    if (threadIdx.x < 2) { s_nw[threadIdx.x] = 0; s_nb[threadIdx.x] = 0; }
    __syncthreads();

    const unsigned* ptrs[2] = {a, b};
    for (int j = 0; j < 2; j++) {
        int nw = 0, nb = 0;
        const unsigned* p = ptrs[j];
        for (int i = threadIdx.x; i < 16384; i += blockDim.x) {
            unsigned w = p[i];
            if (w > 1u) nw = 1;
            if (w & 0xFEFEFEFEu) nb = 1;
        }
        if (nw) atomicOr(&s_nw[j], 1);
        if (nb) atomicOr(&s_nb[j], 1);
    }
    __syncthreads();
    if (threadIdx.x == 0) {
        // is input j a mask?  yes if words-all-01 (i32) or bytes-all-01 (u8)
        int mask1 = (!s_nw[1]) || (!s_nb[1]);
        int mi = mask1 ? 1 : 0;
        g_mask_idx = mi;
        g_mask_is_u8 = (s_nw[mi] != 0);   // words not all 0/1 but it IS a mask -> u8
    }
}

__global__ void init_states_kernel() {
    int i = blockIdx.x * blockDim.x + threadIdx.x;
    if (i < NTILES) g_tile_state[i] = 0ull;
}

__global__ void __launch_bounds__(TPB)
masked_cumsum_kernel(const void* __restrict__ in0,
                     const void* __restrict__ in1,
                     float* __restrict__ out) {
    const int bid  = blockIdx.x;
    const int row  = bid / TILES_PER_ROW;
    const int t    = bid % TILES_PER_ROW;      // tile index within row, 0..31
    const int tid  = threadIdx.x;
    const int lane = tid & 31;
    const int wid  = tid >> 5;

    // uniform pointer selection from probe results
    const int mi = g_mask_idx;
    const float* x        = (const float*)(mi == 0 ? in1 : in0);
    const void*  mask_raw =                (mi == 0 ? in0 : in1);

    const size_t base = (size_t)row * N_COLS + (size_t)t * TILE + (size_t)tid * ITEMS;

    // ---- load 16 floats (4x float4), fully coalesced ----
    float4 xv[4];
    const float4* xp = reinterpret_cast<const float4*>(x + base);
#pragma unroll
    for (int i = 0; i < 4; i++) xv[i] = xp[i];
    const float* xa = reinterpret_cast<const float*>(xv);

    // ---- load mask: dtype selected by probe (uniform branch across grid) ----
    float v[ITEMS];
    if (g_mask_is_u8) {
        const uint8_t* mask = (const uint8_t*)mask_raw;
        const uint4 mv = *reinterpret_cast<const uint4*>(mask + base);
        unsigned mw[4] = {mv.x, mv.y, mv.z, mv.w};
#pragma unroll
        for (int i = 0; i < ITEMS; i++) {
            unsigned b = (mw[i >> 2] >> ((i & 3) * 8)) & 0xFFu;
            v[i] = b ? xa[i] : 0.0f;
        }
    } else {
        const int* mask = (const int*)mask_raw;
        const int4* mp = reinterpret_cast<const int4*>(mask + base);
        int4 m4[4];
#pragma unroll
        for (int i = 0; i < 4; i++) m4[i] = mp[i];
        const int* ma = reinterpret_cast<const int*>(m4);
#pragma unroll
        for (int i = 0; i < ITEMS; i++)
            v[i] = ma[i] ? xa[i] : 0.0f;
    }

    // ---- per-thread serial inclusive scan ----
    float run = 0.0f;
#pragma unroll
    for (int i = 0; i < ITEMS; i++) { run += v[i]; v[i] = run; }
    const float thread_total = run;

    // ---- warp inclusive scan of thread totals ----
    float s = thread_total;
#pragma unroll
    for (int o = 1; o < 32; o <<= 1) {
        float u = __shfl_up_sync(0xFFFFFFFFu, s, o);
        if (lane >= o) s += u;
    }

    __shared__ float warp_sums[TPB / 32];
    __shared__ float s_block_excl;
    if (lane == 31) warp_sums[wid] = s;
    __syncthreads();

    // exclusive prefix of this thread within the block
    float woff = 0.0f;
#pragma unroll
    for (int w = 0; w < TPB / 32; w++)
        woff += (w < wid) ? warp_sums[w] : 0.0f;
    const float thread_excl_in_block = (s - thread_total) + woff;

    // ---- decoupled look-back (warp 0 only) ----
    if (wid == 0) {
        float aggregate = 0.0f;
#pragma unroll
        for (int w = 0; w < TPB / 32; w++) aggregate += warp_sums[w];

        unsigned long long* st_row = g_tile_state + row * TILES_PER_ROW;

        if (t == 0) {
            if (lane == 0) {
                store_state(st_row + 0, pack_state(FLAG_INCL, aggregate));
                s_block_excl = 0.0f;
            }
        } else {
            if (lane == 0)
                store_state(st_row + t, pack_state(FLAG_PART, aggregate));

            // one 32-lane window covers all predecessors (t <= 31)
            const int k = t - 1 - lane;   // lane 0 -> nearest predecessor
            unsigned flag;
            float val;
            if (k >= 0) {
                unsigned long long sv;
                do { sv = load_state(st_row + k); } while ((unsigned)(sv >> 32) == FLAG_INV);
                flag = (unsigned)(sv >> 32);
                val  = __uint_as_float((unsigned)(sv & 0xFFFFFFFFull));
            } else {
                flag = FLAG_INCL;   // virtual "before row start" tile
                val  = 0.0f;
            }

            // closest lane holding an INCLUSIVE prefix; guaranteed to exist (lane t has k=-1)
            const unsigned incl = __ballot_sync(0xFFFFFFFFu, flag == FLAG_INCL);
            const int first = __ffs(incl) - 1;

            float contrib = (lane <= first) ? val : 0.0f;
#pragma unroll
            for (int o = 16; o > 0; o >>= 1)
                contrib += __shfl_xor_sync(0xFFFFFFFFu, contrib, o);
            const float exclusive = contrib;

            if (lane == 0) {
                store_state(st_row + t, pack_state(FLAG_INCL, exclusive + aggregate));
                s_block_excl = exclusive;
            }
        }
    }
    __syncthreads();

    // ---- apply offsets and store (4x float4) ----
    const float offset = s_block_excl + thread_excl_in_block;
    float4 ov[4];
    float* oa = reinterpret_cast<float*>(ov);
#pragma unroll
    for (int i = 0; i < ITEMS; i++) oa[i] = v[i] + offset;

    float4* op = reinterpret_cast<float4*>(out + base);
#pragma unroll
    for (int i = 0; i < 4; i++) op[i] = ov[i];
}

extern "C" void kernel_launch(void* const* d_in, const int* in_sizes, int n_in,
                              void* d_out, int out_size) {
    const void* in0 = d_in[0];
    const void* in1 = d_in[1];
    float*      out = (float*)d_out;

    probe_kernel<<<1, 256>>>((const unsigned*)in0, (const unsigned*)in1);
    init_states_kernel<<<(NTILES + 255) / 256, 256>>>();
    masked_cumsum_kernel<<<NTILES, TPB>>>(in0, in1, out);
}

// round 15
// speedup vs baseline: 1.0808x; 1.0808x over previous
#include <cuda_runtime.h>
#include <cstdint>

// Masked cumulative sum along rows.
// x: [256, 131072] fp32; mask: [256, 131072] bool (u8 OR int32; order in d_in unknown).
// out = cumsum(where(mask, x, 0), axis=1)
//
// Single-pass decoupled look-back scan (validated R8: rel_err 1.7e-7, 125.4us).
// R9: probe fused into init kernel -> 2 launches (saves ~14us, aligns ncu on main kernel).
// R10: ITEMS 16 -> 32 (tile 8192): doubles per-thread LDG batch (MLP), halves tile count
//      and look-back overhead per byte. Look-back depth <= 15 still fits one warp window.

#define N_COLS 131072
#define B_ROWS 256
#define TPB 256
#define ITEMS 32
#define TILE (TPB * ITEMS)                 // 8192
#define TILES_PER_ROW (N_COLS / TILE)      // 16
#define NTILES (B_ROWS * TILES_PER_ROW)    // 4096
#define INIT_BLOCKS (NTILES / TPB)         // 16

#define FLAG_INV  0u
#define FLAG_PART 1u
#define FLAG_INCL 2u

__device__ unsigned long long g_tile_state[NTILES];
__device__ int g_mask_idx;    // which of d_in[0]/d_in[1] is the mask
__device__ int g_mask_is_u8;  // 1 = u8 mask, 0 = int32 mask

__device__ __forceinline__ unsigned long long pack_state(unsigned flag, float v) {
    return ((unsigned long long)flag << 32) | (unsigned long long)__float_as_uint(v);
}

__device__ __forceinline__ void store_state(unsigned long long* p, unsigned long long v) {
    asm volatile("st.global.release.gpu.u64 [%0], %1;" :: "l"(p), "l"(v) : "memory");
}

__device__ __forceinline__ unsigned long long load_state(unsigned long long* p) {
    unsigned long long v;
    asm volatile("ld.global.acquire.gpu.u64 %0, [%1];" : "=l"(v) : "l"(p) : "memory");
    return v;
}

// One launch: blocks 0..INIT_BLOCKS-1 zero the tile states; block INIT_BLOCKS probes
// both input buffers (2048 words = 8 KiB each) to classify mask index + dtype.
//   word-class (all 32-bit words <= 1)       -> int32 0/1 mask
//   byte-class (all bytes in {0,1})          -> u8 0/1 mask
//   neither                                  -> fp32 data
__global__ void init_and_probe_kernel(const unsigned* __restrict__ a,
                                      const unsigned* __restrict__ b) {
    if (blockIdx.x < INIT_BLOCKS) {
        g_tile_state[blockIdx.x * TPB + threadIdx.x] = 0ull;
        return;
    }
    __shared__ int s_nw[2];   // "not all words 0/1"
    __shared__ int s_nb[2];   // "not all bytes 0/1"
    if (threadIdx.x < 2) { s_nw[threadIdx.x] = 0; s_nb[threadIdx.x] = 0; }
    __syncthreads();

    const unsigned* ptrs[2] = {a, b};
#pragma unroll
    for (int j = 0; j < 2; j++) {
        int nw = 0, nb = 0;
        const unsigned* p = ptrs[j];
#pragma unroll
        for (int r = 0; r < 8; r++) {
            unsigned w = p[r * 256 + threadIdx.x];
            if (w > 1u) nw = 1;
            if (w & 0xFEFEFEFEu) nb = 1;
        }
        if (nw) atomicOr(&s_nw[j], 1);
        if (nb) atomicOr(&s_nb[j], 1);
    }
    __syncthreads();
    if (threadIdx.x == 0) {
        int mask1 = (!s_nw[1]) || (!s_nb[1]);   // is input 1 a mask?
        int mi = mask1 ? 1 : 0;
        g_mask_idx = mi;
        g_mask_is_u8 = (s_nw[mi] != 0);         // a mask whose words aren't all 0/1 -> u8
    }
}

__global__ void __launch_bounds__(TPB)
masked_cumsum_kernel(const void* __restrict__ in0,
                     const void* __restrict__ in1,
                     float* __restrict__ out) {
    const int bid  = blockIdx.x;
    const int row  = bid / TILES_PER_ROW;
    const int t    = bid % TILES_PER_ROW;      // tile index within row, 0..15
    const int tid  = threadIdx.x;
    const int lane = tid & 31;
    const int wid  = tid >> 5;

    // uniform pointer selection from probe results
    const int mi = g_mask_idx;
    const float* __restrict__ x  = (const float*)(mi == 0 ? in1 : in0);
    const void*  mask_raw        =               (mi == 0 ? in0 : in1);

    const size_t base = (size_t)row * N_COLS + (size_t)t * TILE + (size_t)tid * ITEMS;

    // ---- load 32 floats (8x float4), fully coalesced, front-batched for MLP ----
    float4 xv[8];
    const float4* __restrict__ xp = reinterpret_cast<const float4*>(x + base);
#pragma unroll
    for (int i = 0; i < 8; i++) xv[i] = xp[i];
    const float* xa = reinterpret_cast<const float*>(xv);

    // ---- load mask: dtype selected by probe (uniform branch across grid) ----
    float v[ITEMS];
    if (g_mask_is_u8) {
        const uint4* __restrict__ mp =
            reinterpret_cast<const uint4*>((const uint8_t*)mask_raw + base);
        uint4 mv[2];
#pragma unroll
        for (int i = 0; i < 2; i++) mv[i] = mp[i];
        const unsigned* mw = reinterpret_cast<const unsigned*>(mv);
#pragma unroll
        for (int i = 0; i < ITEMS; i++) {
            unsigned b = (mw[i >> 2] >> ((i & 3) * 8)) & 0xFFu;
            v[i] = b ? xa[i] : 0.0f;
        }
    } else {
        const int4* __restrict__ mp =
            reinterpret_cast<const int4*>((const int*)mask_raw + base);
        int4 m4[8];
#pragma unroll
        for (int i = 0; i < 8; i++) m4[i] = mp[i];
        const int* ma = reinterpret_cast<const int*>(m4);
#pragma unroll
        for (int i = 0; i < ITEMS; i++)
            v[i] = ma[i] ? xa[i] : 0.0f;
    }

    // ---- per-thread serial inclusive scan ----
    float run = 0.0f;
#pragma unroll
    for (int i = 0; i < ITEMS; i++) { run += v[i]; v[i] = run; }
    const float thread_total = run;

    // ---- warp inclusive scan of thread totals ----
    float s = thread_total;
#pragma unroll
    for (int o = 1; o < 32; o <<= 1) {
        float u = __shfl_up_sync(0xFFFFFFFFu, s, o);
        if (lane >= o) s += u;
    }

    __shared__ float warp_sums[TPB / 32];
    __shared__ float s_block_excl;
    if (lane == 31) warp_sums[wid] = s;
    __syncthreads();

    // exclusive prefix of this thread within the block
    float woff = 0.0f;
#pragma unroll
    for (int w = 0; w < TPB / 32; w++)
        woff += (w < wid) ? warp_sums[w] : 0.0f;
    const float thread_excl_in_block = (s - thread_total) + woff;

    // ---- decoupled look-back (warp 0 only) ----
    if (wid == 0) {
        float aggregate = 0.0f;
#pragma unroll
        for (int w = 0; w < TPB / 32; w++) aggregate += warp_sums[w];

        unsigned long long* st_row = g_tile_state + row * TILES_PER_ROW;

        if (t == 0) {
            if (lane == 0) {
                store_state(st_row + 0, pack_state(FLAG_INCL, aggregate));
                s_block_excl = 0.0f;
            }
        } else {
            if (lane == 0)
                store_state(st_row + t, pack_state(FLAG_PART, aggregate));

            // one 32-lane window covers all predecessors (t <= 15)
            const int k = t - 1 - lane;   // lane 0 -> nearest predecessor
            unsigned flag;
            float val;
            if (k >= 0) {
                unsigned long long sv;
                do { sv = load_state(st_row + k); } while ((unsigned)(sv >> 32) == FLAG_INV);
                flag = (unsigned)(sv >> 32);
                val  = __uint_as_float((unsigned)(sv & 0xFFFFFFFFull));
            } else {
                flag = FLAG_INCL;   // virtual "before row start" tile
                val  = 0.0f;
            }

            // closest lane holding an INCLUSIVE prefix; guaranteed to exist (lane t has k=-1)
            const unsigned incl = __ballot_sync(0xFFFFFFFFu, flag == FLAG_INCL);
            const int first = __ffs(incl) - 1;

            float contrib = (lane <= first) ? val : 0.0f;
#pragma unroll
            for (int o = 16; o > 0; o >>= 1)
                contrib += __shfl_xor_sync(0xFFFFFFFFu, contrib, o);
            const float exclusive = contrib;

            if (lane == 0) {
                store_state(st_row + t, pack_state(FLAG_INCL, exclusive + aggregate));
                s_block_excl = exclusive;
            }
        }
    }
    __syncthreads();

    // ---- apply offsets and store (8x float4) ----
    const float offset = s_block_excl + thread_excl_in_block;
    float4* op = reinterpret_cast<float4*>(out + base);
#pragma unroll
    for (int i = 0; i < 8; i++) {
        float4 o4;
        o4.x = v[i * 4 + 0] + offset;
        o4.y = v[i * 4 + 1] + offset;
        o4.z = v[i * 4 + 2] + offset;
        o4.w = v[i * 4 + 3] + offset;
        op[i] = o4;
    }
}

extern "C" void kernel_launch(void* const* d_in, const int* in_sizes, int n_in,
                              void* d_out, int out_size) {
    const void* in0 = d_in[0];
    const void* in1 = d_in[1];
    float*      out = (float*)d_out;

    init_and_probe_kernel<<<INIT_BLOCKS + 1, TPB>>>((const unsigned*)in0,
                                                    (const unsigned*)in1);
    masked_cumsum_kernel<<<NTILES, TPB>>>(in0, in1, out);
}